// round 1
// baseline (speedup 1.0000x reference)
#include <cuda_runtime.h>
#include <cstdint>

#define N_NODES 100000
#define N_EDGES 600000
#define K_TOT   384          // 3 relations x 128
#define OUT_C   128

// Scratch: agg[N_NODES][384], relation r occupies columns [r*128, r*128+128)
__device__ float g_agg[(size_t)N_NODES * K_TOT];

// ---------------------------------------------------------------------------
// 1) zero the aggregation buffer
// ---------------------------------------------------------------------------
__global__ void zero_agg_kernel() {
    size_t i = (size_t)blockIdx.x * blockDim.x + threadIdx.x;
    size_t n4 = (size_t)N_NODES * K_TOT / 4;
    if (i < n4) {
        reinterpret_cast<float4*>(g_agg)[i] = make_float4(0.f, 0.f, 0.f, 0.f);
    }
}

// ---------------------------------------------------------------------------
// 2) edge scatter: one warp per edge; lane handles a float4 of the 128-wide row
//    agg[dst][rel*128 + lane*4 .. +3] += x[src][lane*4 .. +3]
// ---------------------------------------------------------------------------
__global__ void scatter_kernel(const float4* __restrict__ x4,
                               const int* __restrict__ s0, const int* __restrict__ d0,
                               const int* __restrict__ s1, const int* __restrict__ d1,
                               const int* __restrict__ s2, const int* __restrict__ d2) {
    unsigned gw   = (blockIdx.x * blockDim.x + threadIdx.x) >> 5;
    int      lane = threadIdx.x & 31;
    if (gw >= 3u * N_EDGES) return;

    int rel, e;
    const int* sp;
    const int* dp;
    if (gw < (unsigned)N_EDGES)            { rel = 0; e = gw;                sp = s0; dp = d0; }
    else if (gw < 2u * (unsigned)N_EDGES)  { rel = 1; e = gw - N_EDGES;      sp = s1; dp = d1; }
    else                                   { rel = 2; e = gw - 2u * N_EDGES; sp = s2; dp = d2; }

    int s = __ldg(sp + e);
    int d = __ldg(dp + e);

    float4 v = __ldg(&x4[(size_t)s * (OUT_C / 4) + lane]);

    float* dst = g_agg + (size_t)d * K_TOT + rel * 128 + lane * 4;
    asm volatile("red.global.add.v4.f32 [%0], {%1,%2,%3,%4};"
                 :: "l"(dst), "f"(v.x), "f"(v.y), "f"(v.z), "f"(v.w)
                 : "memory");
}

// ---------------------------------------------------------------------------
// 3) out = relu(agg @ Wcat), Wcat[384][128] = [W0;W1;W2] staged in smem.
//    Block = 256 threads = 8 warps, 64 rows/block (8 rows/warp).
//    Each lane owns 4 consecutive output columns (lane*4..lane*4+3) -> LDS.128
//    for W and STG.128 for out.
// ---------------------------------------------------------------------------
__global__ void gemm_relu_kernel(const float* __restrict__ W0,
                                 const float* __restrict__ W1,
                                 const float* __restrict__ W2,
                                 float* __restrict__ out) {
    extern __shared__ float Ws[];   // [384][128] = 192 KB

    int tid = threadIdx.x;

    // Stage Wcat into smem as float4s (12288 float4 total, 48 per thread).
    for (int i = tid; i < (K_TOT * OUT_C) / 4; i += blockDim.x) {
        int k = i >> 5;           // row of Wcat (0..383)
        int c4 = i & 31;          // float4 index within the 128-wide row
        const float* Wp = (k < 128) ? W0 : (k < 256 ? W1 : W2);
        int kin = k & 127;
        reinterpret_cast<float4*>(Ws)[i] =
            reinterpret_cast<const float4*>(Wp + (size_t)kin * OUT_C)[c4];
    }
    __syncthreads();

    int warp = tid >> 5;
    int lane = tid & 31;
    int row0 = blockIdx.x * 64 + warp * 8;
    if (row0 >= N_NODES) return;     // whole warp inactive (N % 8 == 0); only barrier above

    float4 acc[8];
    #pragma unroll
    for (int r = 0; r < 8; r++) acc[r] = make_float4(0.f, 0.f, 0.f, 0.f);

    const float4* agg4 = reinterpret_cast<const float4*>(g_agg);
    const float4* Ws4  = reinterpret_cast<const float4*>(Ws);

    #pragma unroll 1
    for (int k4 = 0; k4 < K_TOT / 4; k4++) {
        int k = k4 * 4;
        // 4 W rows, lane's 4 columns each: LDS.128 x4
        float4 w0 = Ws4[(size_t)(k + 0) * 32 + lane];
        float4 w1 = Ws4[(size_t)(k + 1) * 32 + lane];
        float4 w2 = Ws4[(size_t)(k + 2) * 32 + lane];
        float4 w3 = Ws4[(size_t)(k + 3) * 32 + lane];

        #pragma unroll
        for (int r = 0; r < 8; r++) {
            float4 a = agg4[((size_t)(row0 + r) * K_TOT + k) >> 2];  // broadcast LDG.128
            acc[r].x += a.x * w0.x + a.y * w1.x + a.z * w2.x + a.w * w3.x;
            acc[r].y += a.x * w0.y + a.y * w1.y + a.z * w2.y + a.w * w3.y;
            acc[r].z += a.x * w0.z + a.y * w1.z + a.z * w2.z + a.w * w3.z;
            acc[r].w += a.x * w0.w + a.y * w1.w + a.z * w2.w + a.w * w3.w;
        }
    }

    #pragma unroll
    for (int r = 0; r < 8; r++) {
        float4 v;
        v.x = fmaxf(acc[r].x, 0.f);
        v.y = fmaxf(acc[r].y, 0.f);
        v.z = fmaxf(acc[r].z, 0.f);
        v.w = fmaxf(acc[r].w, 0.f);
        reinterpret_cast<float4*>(out)[((size_t)(row0 + r) * OUT_C) / 4 + lane] = v;
    }
}

// ---------------------------------------------------------------------------
// launch
// ---------------------------------------------------------------------------
extern "C" void kernel_launch(void* const* d_in, const int* in_sizes, int n_in,
                              void* d_out, int out_size) {
    const float* x  = (const float*)d_in[0];
    const float* W0 = (const float*)d_in[1];
    const float* W1 = (const float*)d_in[2];
    const float* W2 = (const float*)d_in[3];
    const int* s0 = (const int*)d_in[4];
    const int* d0 = (const int*)d_in[5];
    const int* s1 = (const int*)d_in[6];
    const int* d1 = (const int*)d_in[7];
    const int* s2 = (const int*)d_in[8];
    const int* d2 = (const int*)d_in[9];
    float* out = (float*)d_out;

    // 1) zero agg
    {
        size_t n4 = (size_t)N_NODES * K_TOT / 4;   // 9.6M float4
        int threads = 256;
        int blocks = (int)((n4 + threads - 1) / threads);
        zero_agg_kernel<<<blocks, threads>>>();
    }

    // 2) scatter (one warp per edge, all 3 relations in one grid)
    {
        long long total_threads = 3LL * N_EDGES * 32;
        int threads = 256;
        int blocks = (int)((total_threads + threads - 1) / threads);
        scatter_kernel<<<blocks, threads>>>(
            reinterpret_cast<const float4*>(x), s0, d0, s1, d1, s2, d2);
    }

    // 3) fused GEMM + relu
    {
        static bool attr_set = false;   // idempotent attribute set (not a work guard)
        if (!attr_set) {
            cudaFuncSetAttribute(gemm_relu_kernel,
                                 cudaFuncAttributeMaxDynamicSharedMemorySize,
                                 K_TOT * OUT_C * (int)sizeof(float));
            attr_set = true;
        }
        int blocks = (N_NODES + 63) / 64;
        gemm_relu_kernel<<<blocks, 256, K_TOT * OUT_C * sizeof(float)>>>(W0, W1, W2, out);
    }
}

// round 3
// speedup vs baseline: 2.1698x; 2.1698x over previous
#include <cuda_runtime.h>
#include <cstdint>

#define N_NODES 100000
#define N_EDGES 600000
#define IN_C    128
#define OUT_C   128
#define M_TILE  128
#define N_TILES ((N_NODES + M_TILE - 1) / M_TILE)   // 782
#define M_PAD   (N_TILES * M_TILE)                  // 100096
#define KCH     32                                  // K per staged chunk
#define NCHUNK  (IN_C / KCH)                        // 4
#define AS_STRIDE 36                                // padded floats per A row
#define BS_STRIDE 136                               // padded floats per B row
#define AS_BUF   (M_TILE * AS_STRIDE)               // 4608 floats
#define BS_BUF   (KCH * BS_STRIDE)                  // 4352 floats
#define SMEM_FLOATS (2 * (AS_BUF + BS_BUF))
#define SMEM_BYTES  (SMEM_FLOATS * 4)               // 71680

// h[r][M_PAD][128] : per-relation transformed features (pad rows never gathered)
__device__ float g_h[(size_t)3 * M_PAD * OUT_C];

static __device__ __forceinline__ uint32_t tf32_rna(float x) {
    uint32_t y;
    asm("cvt.rna.tf32.f32 %0, %1;" : "=r"(y) : "f"(x));
    return y;
}

// ---------------------------------------------------------------------------
// 1) GEMM: h_j = x @ W_j via mma.sync.m16n8k8.tf32 (HMMA).
//    Grid (782, 3): one 128x128 tile per CTA; K=128 in 4 staged chunks of 32.
//    8 warps -> warp tile 64x32 (2x4 warp grid).
// ---------------------------------------------------------------------------
__global__ __launch_bounds__(256, 2) void gemm_hmma_kernel(
        const float4* __restrict__ x4,
        const float* __restrict__ W0,
        const float* __restrict__ W1,
        const float* __restrict__ W2) {
    extern __shared__ float smem[];
    float* As[2] = { smem,                smem + AS_BUF };
    float* Bs[2] = { smem + 2 * AS_BUF,   smem + 2 * AS_BUF + BS_BUF };

    int tid  = threadIdx.x;
    int lane = tid & 31;
    int wid  = tid >> 5;
    int wr   = wid >> 2;          // 0..1  (64-row slab)
    int wc   = wid & 3;           // 0..3  (32-col slab)
    int g    = lane >> 2;         // group id 0..7
    int tg   = lane & 3;          // thread-in-group 0..3

    int tile_row0 = blockIdx.x * M_TILE;
    const float* Wj = (blockIdx.y == 0) ? W0 : (blockIdx.y == 1 ? W1 : W2);
    float* hj = g_h + (size_t)blockIdx.y * M_PAD * OUT_C;

    // stage chunk c into buffer b (fp32 -> tf32 at STS time)
    auto stage = [&](int c, int b) {
        float* A = As[b];
        float* B = Bs[b];
        #pragma unroll
        for (int i = tid; i < 1024; i += 256) {          // A: 128 rows x 8 f4
            int row = i >> 3, c4 = i & 7;
            int srow = tile_row0 + row;
            if (srow >= N_NODES) srow = 0;               // pad rows: any value
            float4 v = __ldg(x4 + (size_t)srow * (IN_C / 4) + c * 8 + c4);
            uint32_t* p = reinterpret_cast<uint32_t*>(A + row * AS_STRIDE + c4 * 4);
            p[0] = tf32_rna(v.x); p[1] = tf32_rna(v.y);
            p[2] = tf32_rna(v.z); p[3] = tf32_rna(v.w);
        }
        #pragma unroll
        for (int i = tid; i < 1024; i += 256) {          // B: 32 k-rows x 32 f4
            int k = i >> 5, n4 = i & 31;
            float4 v = __ldg(reinterpret_cast<const float4*>(
                             Wj + (size_t)(c * KCH + k) * OUT_C) + n4);
            uint32_t* p = reinterpret_cast<uint32_t*>(B + k * BS_STRIDE + n4 * 4);
            p[0] = tf32_rna(v.x); p[1] = tf32_rna(v.y);
            p[2] = tf32_rna(v.z); p[3] = tf32_rna(v.w);
        }
    };

    float acc[4][4][4];
    #pragma unroll
    for (int mt = 0; mt < 4; mt++)
        #pragma unroll
        for (int nt = 0; nt < 4; nt++)
            #pragma unroll
            for (int r = 0; r < 4; r++) acc[mt][nt][r] = 0.f;

    stage(0, 0);
    __syncthreads();

    for (int c = 0; c < NCHUNK; c++) {
        int b = c & 1;
        if (c + 1 < NCHUNK) stage(c + 1, b ^ 1);

        const uint32_t* A = reinterpret_cast<const uint32_t*>(As[b]);
        const uint32_t* B = reinterpret_cast<const uint32_t*>(Bs[b]);

        #pragma unroll
        for (int ks = 0; ks < KCH / 8; ks++) {
            int kk = ks * 8;
            uint32_t af[4][4], bf[4][2];
            #pragma unroll
            for (int mt = 0; mt < 4; mt++) {
                int m0 = wr * 64 + mt * 16 + g;
                af[mt][0] = A[(m0)     * AS_STRIDE + kk + tg];
                af[mt][1] = A[(m0 + 8) * AS_STRIDE + kk + tg];
                af[mt][2] = A[(m0)     * AS_STRIDE + kk + tg + 4];
                af[mt][3] = A[(m0 + 8) * AS_STRIDE + kk + tg + 4];
            }
            #pragma unroll
            for (int nt = 0; nt < 4; nt++) {
                int n0 = wc * 32 + nt * 8 + g;
                bf[nt][0] = B[(kk + tg)     * BS_STRIDE + n0];
                bf[nt][1] = B[(kk + tg + 4) * BS_STRIDE + n0];
            }
            #pragma unroll
            for (int mt = 0; mt < 4; mt++)
                #pragma unroll
                for (int nt = 0; nt < 4; nt++) {
                    asm volatile(
                        "mma.sync.aligned.m16n8k8.row.col.f32.tf32.tf32.f32 "
                        "{%0,%1,%2,%3}, {%4,%5,%6,%7}, {%8,%9}, {%0,%1,%2,%3};"
                        : "+f"(acc[mt][nt][0]), "+f"(acc[mt][nt][1]),
                          "+f"(acc[mt][nt][2]), "+f"(acc[mt][nt][3])
                        : "r"(af[mt][0]), "r"(af[mt][1]),
                          "r"(af[mt][2]), "r"(af[mt][3]),
                          "r"(bf[nt][0]), "r"(bf[nt][1]));
                }
        }
        __syncthreads();
    }

    // epilogue: write h tile (pad rows written but never gathered)
    #pragma unroll
    for (int mt = 0; mt < 4; mt++) {
        int row = tile_row0 + wr * 64 + mt * 16 + g;
        #pragma unroll
        for (int nt = 0; nt < 4; nt++) {
            int col = wc * 32 + nt * 8 + 2 * tg;
            float2* p0 = reinterpret_cast<float2*>(hj + (size_t)row * OUT_C + col);
            float2* p1 = reinterpret_cast<float2*>(hj + (size_t)(row + 8) * OUT_C + col);
            *p0 = make_float2(acc[mt][nt][0], acc[mt][nt][1]);
            *p1 = make_float2(acc[mt][nt][2], acc[mt][nt][3]);
        }
    }
}

// ---------------------------------------------------------------------------
// 2) zero d_out
// ---------------------------------------------------------------------------
__global__ void zero_out_kernel(float4* __restrict__ out4) {
    size_t i = (size_t)blockIdx.x * blockDim.x + threadIdx.x;
    if (i < (size_t)N_NODES * OUT_C / 4)
        out4[i] = make_float4(0.f, 0.f, 0.f, 0.f);
}

// ---------------------------------------------------------------------------
// 3) scatter: out[dst] += h_r[src]; one warp per edge, lane owns a float4.
//    RED destination (51 MB) is L2-resident.
// ---------------------------------------------------------------------------
__global__ void scatter_kernel(float* __restrict__ out,
                               const int* __restrict__ s0, const int* __restrict__ d0,
                               const int* __restrict__ s1, const int* __restrict__ d1,
                               const int* __restrict__ s2, const int* __restrict__ d2) {
    unsigned gw   = (blockIdx.x * blockDim.x + threadIdx.x) >> 5;
    int      lane = threadIdx.x & 31;
    if (gw >= 3u * N_EDGES) return;

    int rel, e;
    const int* sp;
    const int* dp;
    if (gw < (unsigned)N_EDGES)            { rel = 0; e = gw;                sp = s0; dp = d0; }
    else if (gw < 2u * (unsigned)N_EDGES)  { rel = 1; e = gw - N_EDGES;      sp = s1; dp = d1; }
    else                                   { rel = 2; e = gw - 2u * N_EDGES; sp = s2; dp = d2; }

    int s = __ldg(sp + e);
    int d = __ldg(dp + e);

    const float4* h4 = reinterpret_cast<const float4*>(
        g_h + (size_t)rel * M_PAD * OUT_C);
    float4 v = __ldg(h4 + (size_t)s * (OUT_C / 4) + lane);

    float* dst = out + (size_t)d * OUT_C + lane * 4;
    asm volatile("red.global.add.v4.f32 [%0], {%1,%2,%3,%4};"
                 :: "l"(dst), "f"(v.x), "f"(v.y), "f"(v.z), "f"(v.w)
                 : "memory");
}

// ---------------------------------------------------------------------------
// 4) relu in place
// ---------------------------------------------------------------------------
__global__ void relu_kernel(float4* __restrict__ out4) {
    size_t i = (size_t)blockIdx.x * blockDim.x + threadIdx.x;
    if (i < (size_t)N_NODES * OUT_C / 4) {
        float4 v = out4[i];
        v.x = fmaxf(v.x, 0.f); v.y = fmaxf(v.y, 0.f);
        v.z = fmaxf(v.z, 0.f); v.w = fmaxf(v.w, 0.f);
        out4[i] = v;
    }
}

// ---------------------------------------------------------------------------
// launch
// ---------------------------------------------------------------------------
extern "C" void kernel_launch(void* const* d_in, const int* in_sizes, int n_in,
                              void* d_out, int out_size) {
    const float* x  = (const float*)d_in[0];
    const float* W0 = (const float*)d_in[1];
    const float* W1 = (const float*)d_in[2];
    const float* W2 = (const float*)d_in[3];
    const int* s0 = (const int*)d_in[4];
    const int* d0 = (const int*)d_in[5];
    const int* s1 = (const int*)d_in[6];
    const int* d1 = (const int*)d_in[7];
    const int* s2 = (const int*)d_in[8];
    const int* d2 = (const int*)d_in[9];
    float* out = (float*)d_out;

    // 1) GEMM-first: h_r = x @ W_r (tensor cores, tf32)
    {
        static bool attr_set = false;   // idempotent attribute set
        if (!attr_set) {
            cudaFuncSetAttribute(gemm_hmma_kernel,
                                 cudaFuncAttributeMaxDynamicSharedMemorySize,
                                 SMEM_BYTES);
            attr_set = true;
        }
        dim3 grid(N_TILES, 3);
        gemm_hmma_kernel<<<grid, 256, SMEM_BYTES>>>(
            reinterpret_cast<const float4*>(x), W0, W1, W2);
    }

    // 2) zero the output accumulator
    {
        size_t n4 = (size_t)N_NODES * OUT_C / 4;
        zero_out_kernel<<<(int)((n4 + 255) / 256), 256>>>(
            reinterpret_cast<float4*>(out));
    }

    // 3) scatter h into out (L2-resident destination)
    {
        long long total_threads = 3LL * N_EDGES * 32;
        int blocks = (int)((total_threads + 255) / 256);
        scatter_kernel<<<blocks, 256>>>(out, s0, d0, s1, d1, s2, d2);
    }

    // 4) relu in place
    {
        size_t n4 = (size_t)N_NODES * OUT_C / 4;
        relu_kernel<<<(int)((n4 + 255) / 256), 256>>>(
            reinterpret_cast<float4*>(out));
    }
}